// round 16
// baseline (speedup 1.0000x reference)
#include <cuda_runtime.h>
#include <cuda_fp16.h>
#include <cstdint>

// ---------------- problem constants ----------------
#define NODES 100000
#define EDGES 1600000
#define HIDF  128
#define OUTF  64
#define KTOP  32

// ---------------- scratch (device globals; no allocation allowed) ----------
__device__ float g_h[(size_t)NODES * HIDF];        // dense activations (h0)
__device__ float g_z[(size_t)NODES * HIDF];        // z1 = t1 @ W2
__device__ float g_z2[(size_t)NODES * OUTF];       // z2 = t2 @ Wo
__device__ float g_t1v[(size_t)NODES * KTOP];      // compact t1 values (·souti)
__device__ unsigned char g_t1c[(size_t)NODES * KTOP];
__device__ float g_t2v[(size_t)NODES * KTOP];      // compact t2 values (·souti)
__device__ unsigned char g_t2c[(size_t)NODES * KTOP];
__device__ int   g_degout[NODES];
__device__ int   g_degin[NODES];
__device__ float g_souti[NODES];
__device__ float g_sini[NODES];
__device__ int   g_rowptr[NODES];
__device__ int   g_cursor[NODES];
__device__ int   g_eidx[EDGES];
__device__ int   g_bsum[128];
__device__ float g_c1[HIDF];                       // bg1@W2 + b2
__device__ float g_c2[OUTF];                       // bg2@Wo + bo
__device__ __half g_wbh[2 * 128 * 128];            // W_in^T, W1^T hi
__device__ __half g_wbl[2 * 128 * 128];            // lo

__device__ __forceinline__ uint32_t smem_to_u32(const void* smem_ptr) {
    uint32_t addr;
    asm("{ .reg .u64 tmp; cvta.to.shared.u64 tmp, %1; cvt.u32.u64 %0, tmp; }"
        : "=r"(addr) : "l"(smem_ptr));
    return addr;
}

__device__ __forceinline__ void ldsm_x4(uint32_t r[4], uint32_t addr) {
    asm volatile("ldmatrix.sync.aligned.m8n8.x4.shared.b16 {%0,%1,%2,%3}, [%4];"
        : "=r"(r[0]), "=r"(r[1]), "=r"(r[2]), "=r"(r[3]) : "r"(addr));
}

__device__ __forceinline__ void mma_fp16(float c[4], const uint32_t a[4],
                                         uint32_t b0, uint32_t b1) {
    asm volatile(
        "mma.sync.aligned.m16n8k16.row.col.f32.f16.f16.f32 "
        "{%0,%1,%2,%3}, {%4,%5,%6,%7}, {%8,%9}, {%0,%1,%2,%3};"
        : "+f"(c[0]), "+f"(c[1]), "+f"(c[2]), "+f"(c[3])
        : "r"(a[0]), "r"(a[1]), "r"(a[2]), "r"(a[3]), "r"(b0), "r"(b1));
}

// packed fp16 hi/lo split of 2 floats: hi = rn(v), lo = rn(v - f32(hi)).
// Bit-identical to scalar __float2half path, ~40% fewer issue slots.
__device__ __forceinline__ void split2(float2 p, uint32_t& hi, uint32_t& lo) {
    __half2 h = __float22half2_rn(p);
    float2 hb = __half22float2(h);
    __half2 l = __float22half2_rn(make_float2(p.x - hb.x, p.y - hb.y));
    hi = *(uint32_t*)&h;
    lo = *(uint32_t*)&l;
}

// exact top-32-of-128 threshold via bitwise radix select, warp-collective.
__device__ __forceinline__ unsigned topk_threshold(const unsigned key[4]) {
    unsigned thr = 0u;
#pragma unroll
    for (int b = 31; b >= 0; b--) {
        unsigned cand = thr | (1u << b);
        int local = (key[0] >= cand) + (key[1] >= cand)
                  + (key[2] >= cand) + (key[3] >= cand);
        int cnt = __reduce_add_sync(0xffffffffu, (unsigned)local);
        if (cnt >= KTOP) thr = cand;
    }
    return thr;
}

// ---------------- degree + CSR build kernels ----------------
__global__ void hist_kernel(const int* __restrict__ src, const int* __restrict__ dst, int E) {
    int e = blockIdx.x * blockDim.x + threadIdx.x;
    if (e < E) {
        atomicAdd(&g_degout[src[e]], 1);
        atomicAdd(&g_degin[dst[e]], 1);
    }
}

__global__ void __launch_bounds__(1024) scan_block_kernel(int n) {
    __shared__ int sh[1024];
    int tid = threadIdx.x;
    int i = blockIdx.x * 1024 + tid;
    int v = (i < n) ? g_degin[i] : 0;
    sh[tid] = v;
    __syncthreads();
#pragma unroll
    for (int off = 1; off < 1024; off <<= 1) {
        int t = (tid >= off) ? sh[tid - off] : 0;
        __syncthreads();
        sh[tid] += t;
        __syncthreads();
    }
    if (i < n) g_rowptr[i] = sh[tid] - v;
    if (tid == 1023) g_bsum[blockIdx.x] = sh[1023];
}

__global__ void __launch_bounds__(256) scan_add_kernel(int n, int nb) {
    __shared__ int sh[128];
    int tid = threadIdx.x;
    if (tid < 128) sh[tid] = (tid < nb) ? g_bsum[tid] : 0;
    __syncthreads();
#pragma unroll
    for (int off = 1; off < 128; off <<= 1) {
        int u = 0;
        if (tid < 128 && tid >= off) u = sh[tid - off];
        __syncthreads();
        if (tid < 128) sh[tid] += u;
        __syncthreads();
    }
    int i = blockIdx.x * blockDim.x + tid;
    if (i < n) {
        int blk = i >> 10;
        int base = (blk == 0) ? 0 : sh[blk - 1];
        int r = g_rowptr[i] + base;
        g_rowptr[i] = r;
        g_cursor[i] = r;
        int dout = g_degout[i]; if (dout < 1) dout = 1;
        int din  = g_degin[i];  if (din  < 1) din  = 1;
        g_souti[i] = rsqrtf((float)dout);
        g_sini[i]  = rsqrtf((float)din);
    }
}

__global__ void fill_kernel(const int* __restrict__ src, const int* __restrict__ dst, int E) {
    int e = blockIdx.x * blockDim.x + threadIdx.x;
    if (e < E) {
        int d = dst[e];
        int pos = atomicAdd(&g_cursor[d], 1);
        g_eidx[pos] = src[e];
    }
}

// ---------------- weight prep ------------------------------------------------
__global__ void wsplit_kernel(const float* __restrict__ W_in, const float* __restrict__ W1) {
    int i = blockIdx.x * blockDim.x + threadIdx.x;
    if (i >= 32768) return;
    int layer = i >> 14, idx = i & 16383;
    const float* W = layer ? W1 : W_in;
    int n = idx >> 7, k = idx & 127;
    float v = W[k * 128 + n];
    __half h = __float2half(v);
    __half l = __float2half(v - __half2float(h));
    g_wbh[(layer << 14) + n * 128 + k] = h;
    g_wbl[(layer << 14) + n * 128 + k] = l;
}

// warp-parallel bias folding: c1 = bg1@W2 + b2 (128), c2 = bg2@Wo + bo (64)
__global__ void __launch_bounds__(768) cfold_kernel(
    const float* __restrict__ bg1, const float* __restrict__ W2,
    const float* __restrict__ b2,
    const float* __restrict__ bg2, const float* __restrict__ Wo,
    const float* __restrict__ bo) {
    int wid  = threadIdx.x >> 5;
    int lane = threadIdx.x & 31;
    int o    = wid * 8 + (lane >> 2);
    int l4   = lane & 3;
    if (o < 128) {
        float acc = 0.f;
        for (int k = l4; k < 128; k += 4) acc += bg1[k] * W2[k * 128 + o];
        acc += __shfl_xor_sync(0xffffffffu, acc, 1);
        acc += __shfl_xor_sync(0xffffffffu, acc, 2);
        if (l4 == 0) g_c1[o] = acc + b2[o];
    } else if (o < 192) {
        int n = o - 128;
        float acc = 0.f;
        for (int k = l4; k < 128; k += 4) acc += bg2[k] * Wo[k * 64 + n];
        acc += __shfl_xor_sync(0xffffffffu, acc, 1);
        acc += __shfl_xor_sync(0xffffffffu, acc, 2);
        if (l4 == 0) g_c2[n] = acc + bo[n];
    }
}

// ---------------- HMMA fp16x3 GEMM (+ optional fused MaxK -> compact) -------
template <int BN, bool RELU, bool MAXK>
__global__ void __launch_bounds__(256, 2) hmma_gemm_kernel(
    const float* __restrict__ A,
    const __half* __restrict__ wbh,
    const __half* __restrict__ wbl,
    const float* __restrict__ bias,
    float* __restrict__ C,
    float* __restrict__ TV, unsigned char* __restrict__ TC, int M)
{
    static_assert(!MAXK || BN == 128, "fused maxk needs full rows per block");
    constexpr int NW = BN / 32;
    constexpr int MW = 8 / NW;
    constexpr int BM = MW * 32;
    constexpr int LDB = 272;
    constexpr int OFF_AH = 0;
    constexpr int OFF_AL = OFF_AH + BM * LDB;
    constexpr int OFF_WH = OFF_AL + BM * LDB;
    constexpr int OFF_WL = OFF_WH + BN * LDB;
    constexpr int OFF_BI = OFF_WL + BN * LDB;

    extern __shared__ char smem[];
    const uint32_t sb = smem_to_u32(smem);
    const int tid  = threadIdx.x;
    const int wid  = tid >> 5;
    const int lane = tid & 31;
    const int row0 = blockIdx.x * BM;
    const int warp_m = wid / NW;
    const int warp_n = wid % NW;

    for (int i = tid; i < BN * 64; i += 256) {
        int n = i >> 6, kp = i & 63;
        ((uint32_t*)(smem + OFF_WH + n * LDB))[kp] = ((const uint32_t*)wbh)[i];
        ((uint32_t*)(smem + OFF_WL + n * LDB))[kp] = ((const uint32_t*)wbl)[i];
    }
    if (tid < BN) ((float*)(smem + OFF_BI))[tid] = bias[tid];

    for (int i = tid; i < BM * 32; i += 256) {
        int r = i >> 5, c4 = i & 31;
        float4 v = make_float4(0.f, 0.f, 0.f, 0.f);
        if (row0 + r < M) v = ((const float4*)A)[(size_t)(row0 + r) * 32 + c4];
        uint32_t h0, l0, h1, l1;
        split2(make_float2(v.x, v.y), h0, l0);
        split2(make_float2(v.z, v.w), h1, l1);
        uint32_t* dh = (uint32_t*)(smem + OFF_AH + r * LDB);
        uint32_t* dl = (uint32_t*)(smem + OFF_AL + r * LDB);
        dh[c4 * 2]     = h0;
        dh[c4 * 2 + 1] = h1;
        dl[c4 * 2]     = l0;
        dl[c4 * 2 + 1] = l1;
    }
    __syncthreads();

    const int a_row  = warp_m * 32 + (lane & 15);
    const int a_koff = (lane >> 4) * 8;
    const int b_row  = warp_n * 32 + (lane & 7) + ((lane >> 4) << 3);
    const int b_koff = ((lane >> 3) & 1) * 8;

    float acc[2][4][4];
#pragma unroll
    for (int mt = 0; mt < 2; mt++)
#pragma unroll
        for (int nt = 0; nt < 4; nt++)
#pragma unroll
            for (int q = 0; q < 4; q++) acc[mt][nt][q] = 0.f;

#pragma unroll
    for (int kt = 0; kt < 8; kt++) {
        const int kb = kt * 32 + a_koff * 2;
        uint32_t ah[2][4], al[2][4], wh[2][4], wl[2][4];
#pragma unroll
        for (int mt = 0; mt < 2; mt++) {
            uint32_t addr = sb + OFF_AH + (uint32_t)(a_row + mt * 16) * LDB + kb;
            ldsm_x4(ah[mt], addr);
            ldsm_x4(al[mt], addr + (OFF_AL - OFF_AH));
        }
        const int kbB = kt * 32 + b_koff * 2;
#pragma unroll
        for (int p = 0; p < 2; p++) {
            uint32_t addr = sb + OFF_WH + (uint32_t)(b_row + p * 16) * LDB + kbB;
            ldsm_x4(wh[p], addr);
            ldsm_x4(wl[p], addr + (OFF_WL - OFF_WH));
        }
#pragma unroll
        for (int mt = 0; mt < 2; mt++) {
#pragma unroll
            for (int p = 0; p < 2; p++) {
                mma_fp16(acc[mt][2 * p],     ah[mt], wh[p][0], wh[p][1]);
                mma_fp16(acc[mt][2 * p],     ah[mt], wl[p][0], wl[p][1]);
                mma_fp16(acc[mt][2 * p],     al[mt], wh[p][0], wh[p][1]);
                mma_fp16(acc[mt][2 * p + 1], ah[mt], wh[p][2], wh[p][3]);
                mma_fp16(acc[mt][2 * p + 1], ah[mt], wl[p][2], wl[p][3]);
                mma_fp16(acc[mt][2 * p + 1], al[mt], wh[p][2], wh[p][3]);
            }
        }
    }

    const float* bi = (const float*)(smem + OFF_BI);

    if (MAXK) {
        __syncthreads();
        float* rbuf = (float*)smem;          // [BM][132]
#pragma unroll
        for (int mt = 0; mt < 2; mt++) {
#pragma unroll
            for (int nt = 0; nt < 4; nt++) {
                int r   = warp_m * 32 + mt * 16 + (lane >> 2);
                int col = warp_n * 32 + nt * 8 + (lane & 3) * 2;
                float bx = bi[col], by = bi[col + 1];
                rbuf[r * 132 + col]           = acc[mt][nt][0] + bx;
                rbuf[r * 132 + col + 1]       = acc[mt][nt][1] + by;
                rbuf[(r + 8) * 132 + col]     = acc[mt][nt][2] + bx;
                rbuf[(r + 8) * 132 + col + 1] = acc[mt][nt][3] + by;
            }
        }
        __syncthreads();

        const unsigned lmlt = (1u << lane) - 1u;
#pragma unroll 1
        for (int rr = 0; rr < 8; rr++) {
            int r    = wid * 8 + rr;
            int grow = row0 + r;
            if (grow >= M) break;

            float v[4];
            unsigned key[4];
#pragma unroll
            for (int j = 0; j < 4; j++) {
                v[j] = rbuf[r * 132 + lane + 32 * j];
                unsigned u = __float_as_uint(v[j]);
                key[j] = (u & 0x80000000u) ? ~u : (u | 0x80000000u);
            }
            unsigned thr = topk_threshold(key);
            int rem;
            {
                int lg = (key[0] > thr) + (key[1] > thr)
                       + (key[2] > thr) + (key[3] > thr);
                rem = KTOP - (int)__reduce_add_sync(0xffffffffu, (unsigned)lg);
            }
            const float s = g_souti[grow];
            float* ov = TV + (size_t)grow * KTOP;
            unsigned char* oc = TC + (size_t)grow * KTOP;
            int off = 0;
#pragma unroll
            for (int j = 0; j < 4; j++) {
                unsigned beq = __ballot_sync(0xffffffffu, key[j] == thr);
                int neq  = __popc(beq);
                int take = rem < neq ? rem : neq;
                if (take < 0) take = 0;
                rem -= take;
                bool sel = (key[j] > thr) ||
                           ((key[j] == thr) && (__popc(beq & lmlt) < take));
                unsigned bsel = __ballot_sync(0xffffffffu, sel);
                if (sel) {
                    int pos = off + __popc(bsel & lmlt);
                    ov[pos] = v[j] * s;
                    oc[pos] = (unsigned char)(lane + 32 * j);
                }
                off += __popc(bsel);
            }
        }
    } else {
#pragma unroll
        for (int mt = 0; mt < 2; mt++) {
#pragma unroll
            for (int nt = 0; nt < 4; nt++) {
                int row = row0 + warp_m * 32 + mt * 16 + (lane >> 2);
                int col = warp_n * 32 + nt * 8 + (lane & 3) * 2;
                float bx = bi[col], by = bi[col + 1];
                float2 o0, o1;
                o0.x = acc[mt][nt][0] + bx; o0.y = acc[mt][nt][1] + by;
                o1.x = acc[mt][nt][2] + bx; o1.y = acc[mt][nt][3] + by;
                if (RELU) {
                    o0.x = fmaxf(o0.x, 0.f); o0.y = fmaxf(o0.y, 0.f);
                    o1.x = fmaxf(o1.x, 0.f); o1.y = fmaxf(o1.y, 0.f);
                }
                if (row < M)     *(float2*)&C[(size_t)row * BN + col] = o0;
                if (row + 8 < M) *(float2*)&C[(size_t)(row + 8) * BN + col] = o1;
            }
        }
    }
}

// ---------------- SPMM v3: 512 threads, 128 rows/block -----------------------
template <int NC>
__global__ void __launch_bounds__(512) spmm_kernel(
    const float* __restrict__ tv, const unsigned char* __restrict__ tc,
    const float* __restrict__ W, float* __restrict__ Z, int M)
{
    constexpr int RPB = 128;
    extern __shared__ float smf[];
    float* ws = smf;                                 // [128][NC]
    float* sval = ws + 128 * NC;                     // [RPB][32]
    unsigned char* scol = (unsigned char*)(sval + RPB * 32);

    const int tid  = threadIdx.x;
    const int lane = tid & 31;
    const int wl   = tid >> 5;
    const int row0 = blockIdx.x * RPB;

    for (int i = tid; i < 128 * NC / 4; i += 512)
        ((float4*)ws)[i] = ((const float4*)W)[i];
    {
        int base = row0 * KTOP;
        int lim  = (M - row0) * KTOP;
        if (lim > RPB * KTOP) lim = RPB * KTOP;
        for (int i = tid * 4; i < RPB * KTOP; i += 2048) {
            float4 v = make_float4(0.f, 0.f, 0.f, 0.f);
            uint32_t c = 0;
            if (i < lim) {
                v = *(const float4*)(tv + base + i);
                c = *(const uint32_t*)(tc + base + i);
            }
            *(float4*)(sval + i) = v;
            *(uint32_t*)(scol + i) = c;
        }
    }
    __syncthreads();

#pragma unroll 1
    for (int rr = 0; rr < 8; rr++) {
        const int lr  = wl * 8 + rr;
        const int row = row0 + lr;
        if (row >= M) break;

        const float* vrow = sval + lr * KTOP;
        const unsigned char* crow = scol + lr * KTOP;

        if (NC == 128) {
            float4 acc = make_float4(0.f, 0.f, 0.f, 0.f);
#pragma unroll
            for (int j = 0; j < KTOP; j++) {
                float vj = vrow[j];
                int   cj = crow[j];
                float4 w = ((const float4*)(ws + cj * NC))[lane];
                acc.x += vj * w.x;
                acc.y += vj * w.y;
                acc.z += vj * w.z;
                acc.w += vj * w.w;
            }
            ((float4*)(Z + (size_t)row * NC))[lane] = acc;
        } else {
            float2 acc = make_float2(0.f, 0.f);
#pragma unroll
            for (int j = 0; j < KTOP; j++) {
                float vj = vrow[j];
                int   cj = crow[j];
                float2 w = ((const float2*)(ws + cj * NC))[lane];
                acc.x += vj * w.x;
                acc.y += vj * w.y;
            }
            ((float2*)(Z + (size_t)row * NC))[lane] = acc;
        }
    }
}

// ---------------- gather (128 cols) + fused MaxK -> compact t2 ---------------
__global__ void __launch_bounds__(256) gather_maxk_kernel(int M) {
    __shared__ float rbuf[8][128];
    int w    = (blockIdx.x * blockDim.x + threadIdx.x) >> 5;
    int lane = threadIdx.x & 31;
    int wl   = threadIdx.x >> 5;
    if (w >= M) return;

    float acc0 = 0.f, acc1 = 0.f, acc2 = 0.f, acc3 = 0.f;
    const int beg = g_rowptr[w];
    const int end = beg + g_degin[w];
    const float4* tp = (const float4*)g_z;

    int e = beg;
    for (; e + 8 <= end; e += 8) {
        int s[8];
#pragma unroll
        for (int q = 0; q < 8; q++) s[q] = __ldg(&g_eidx[e + q]);
        float4 v[8];
#pragma unroll
        for (int q = 0; q < 8; q++) v[q] = __ldg(&tp[(size_t)s[q] * 32 + lane]);
#pragma unroll
        for (int q = 0; q < 8; q++) {
            acc0 += v[q].x; acc1 += v[q].y; acc2 += v[q].z; acc3 += v[q].w;
        }
    }
    for (; e < end; e++) {
        int s0 = __ldg(&g_eidx[e]);
        float4 v0 = __ldg(&tp[(size_t)s0 * 32 + lane]);
        acc0 += v0.x; acc1 += v0.y; acc2 += v0.z; acc3 += v0.w;
    }

    const float sc = g_sini[w];
    float4 b = __ldg(&((const float4*)g_c1)[lane]);
    rbuf[wl][lane * 4]     = acc0 * sc + b.x;
    rbuf[wl][lane * 4 + 1] = acc1 * sc + b.y;
    rbuf[wl][lane * 4 + 2] = acc2 * sc + b.z;
    rbuf[wl][lane * 4 + 3] = acc3 * sc + b.w;
    __syncwarp();

    float v[4];
    unsigned key[4];
#pragma unroll
    for (int j = 0; j < 4; j++) {
        v[j] = rbuf[wl][lane + 32 * j];
        unsigned u = __float_as_uint(v[j]);
        key[j] = (u & 0x80000000u) ? ~u : (u | 0x80000000u);
    }
    unsigned thr = topk_threshold(key);
    int rem;
    {
        int lg = (key[0] > thr) + (key[1] > thr)
               + (key[2] > thr) + (key[3] > thr);
        rem = KTOP - (int)__reduce_add_sync(0xffffffffu, (unsigned)lg);
    }
    const float s = g_souti[w];
    const unsigned lmlt = (1u << lane) - 1u;
    float* ov = g_t2v + (size_t)w * KTOP;
    unsigned char* oc = g_t2c + (size_t)w * KTOP;
    int off = 0;
#pragma unroll
    for (int j = 0; j < 4; j++) {
        unsigned beq = __ballot_sync(0xffffffffu, key[j] == thr);
        int neq  = __popc(beq);
        int take = rem < neq ? rem : neq;
        if (take < 0) take = 0;
        rem -= take;
        bool sel = (key[j] > thr) ||
                   ((key[j] == thr) && (__popc(beq & lmlt) < take));
        unsigned bsel = __ballot_sync(0xffffffffu, sel);
        if (sel) {
            int pos = off + __popc(bsel & lmlt);
            ov[pos] = v[j] * s;
            oc[pos] = (unsigned char)(lane + 32 * j);
        }
        off += __popc(bsel);
    }
}

// ---------------- final gather (64 cols) -> d_out ----------------------------
__global__ void __launch_bounds__(256) gather_out_kernel(float* __restrict__ out, int M) {
    int w    = (blockIdx.x * blockDim.x + threadIdx.x) >> 5;
    int lane = threadIdx.x & 31;
    if (w >= M) return;

    float acc0 = 0.f, acc1 = 0.f;
    const int beg = g_rowptr[w];
    const int end = beg + g_degin[w];
    const float2* tp = (const float2*)g_z2;

    int e = beg;
    for (; e + 8 <= end; e += 8) {
        int s[8];
#pragma unroll
        for (int q = 0; q < 8; q++) s[q] = __ldg(&g_eidx[e + q]);
        float2 v[8];
#pragma unroll
        for (int q = 0; q < 8; q++) v[q] = __ldg(&tp[(size_t)s[q] * 32 + lane]);
#pragma unroll
        for (int q = 0; q < 8; q++) { acc0 += v[q].x; acc1 += v[q].y; }
    }
    for (; e < end; e++) {
        int s0 = __ldg(&g_eidx[e]);
        float2 v0 = __ldg(&tp[(size_t)s0 * 32 + lane]);
        acc0 += v0.x; acc1 += v0.y;
    }

    const float sc = g_sini[w];
    float2 b = __ldg(&((const float2*)g_c2)[lane]);
    float2 o;
    o.x = acc0 * sc + b.x;
    o.y = acc1 * sc + b.y;
    ((float2*)(out + (size_t)w * OUTF))[lane] = o;
}

// ---------------- launch -----------------------------------------------------
extern "C" void kernel_launch(void* const* d_in, const int* in_sizes, int n_in,
                              void* d_out, int out_size) {
    const float* x    = (const float*)d_in[0];
    const int*   src  = (const int*)d_in[1];
    const int*   dst  = (const int*)d_in[2];
    const float* W_in = (const float*)d_in[3];
    const float* b_in = (const float*)d_in[4];
    const float* W1   = (const float*)d_in[5];
    const float* b1   = (const float*)d_in[6];
    const float* bg1  = (const float*)d_in[7];
    const float* W2   = (const float*)d_in[8];
    const float* b2   = (const float*)d_in[9];
    const float* bg2  = (const float*)d_in[10];
    const float* Wo   = (const float*)d_in[11];
    const float* bo   = (const float*)d_in[12];
    float* out = (float*)d_out;

    const int M = in_sizes[0] / HIDF;   // 100000
    const int E = in_sizes[1];          // 1600000

    static bool s_init = false;
    static cudaStream_t s1;
    static cudaEvent_t e_root, e_scan, e_fill;
    if (!s_init) {
        cudaStreamCreateWithFlags(&s1, cudaStreamNonBlocking);
        cudaEventCreateWithFlags(&e_root, cudaEventDisableTiming);
        cudaEventCreateWithFlags(&e_scan, cudaEventDisableTiming);
        cudaEventCreateWithFlags(&e_fill, cudaEventDisableTiming);
        s_init = true;
    }

    const int SMEMG128 = (64 + 128) * 2 * 272 + 128 * 4;           // 104960
    const int SMEMS128 = 128 * 128 * 4 + 128 * 32 * 4 + 128 * 32;  // 86016
    const int SMEMS64  = 128 * 64 * 4  + 128 * 32 * 4 + 128 * 32;  // 53248
    cudaFuncSetAttribute((const void*)hmma_gemm_kernel<128, true,  false>, cudaFuncAttributeMaxDynamicSharedMemorySize, SMEMG128);
    cudaFuncSetAttribute((const void*)hmma_gemm_kernel<128, false, true>,  cudaFuncAttributeMaxDynamicSharedMemorySize, SMEMG128);
    cudaFuncSetAttribute((const void*)spmm_kernel<128>, cudaFuncAttributeMaxDynamicSharedMemorySize, SMEMS128);
    cudaFuncSetAttribute((const void*)spmm_kernel<64>,  cudaFuncAttributeMaxDynamicSharedMemorySize, SMEMS64);

    void *ph, *pz, *pz2, *pt1v, *pt1c, *pt2v, *pt2c, *pdo, *pdi, *pwbh, *pwbl;
    cudaGetSymbolAddress(&ph,   g_h);
    cudaGetSymbolAddress(&pz,   g_z);
    cudaGetSymbolAddress(&pz2,  g_z2);
    cudaGetSymbolAddress(&pt1v, g_t1v);
    cudaGetSymbolAddress(&pt1c, g_t1c);
    cudaGetSymbolAddress(&pt2v, g_t2v);
    cudaGetSymbolAddress(&pt2c, g_t2c);
    cudaGetSymbolAddress(&pdo,  g_degout);
    cudaGetSymbolAddress(&pdi,  g_degin);
    cudaGetSymbolAddress(&pwbh, g_wbh);
    cudaGetSymbolAddress(&pwbl, g_wbl);
    float* h = (float*)ph;
    __half* wbh = (__half*)pwbh;
    __half* wbl = (__half*)pwbl;

    const int TB = 256;
    const int g128_grid = (M + 63) / 64;
    const int warp_grid = (M * 32 + TB - 1) / TB;
    const int node_grid = (M + TB - 1) / TB;
    const int edge_grid = (E + TB - 1) / TB;
    const int spmm_grid = (M + 127) / 128;
    const int NB        = (M + 1023) / 1024;

    // fork: CSR build on side stream (cfold at tail — c1/c2 used late)
    cudaEventRecord(e_root, 0);
    cudaStreamWaitEvent(s1, e_root, 0);
    cudaMemsetAsync(pdo, 0, (size_t)M * sizeof(int), s1);
    cudaMemsetAsync(pdi, 0, (size_t)M * sizeof(int), s1);
    hist_kernel<<<edge_grid, TB, 0, s1>>>(src, dst, E);
    scan_block_kernel<<<NB, 1024, 0, s1>>>(M);
    scan_add_kernel<<<node_grid, TB, 0, s1>>>(M, NB);
    cudaEventRecord(e_scan, s1);
    fill_kernel<<<edge_grid, TB, 0, s1>>>(src, dst, E);
    cfold_kernel<<<1, 768, 0, s1>>>(bg1, W2, b2, bg2, Wo, bo);
    cudaEventRecord(e_fill, s1);

    // main: weight split + input projection
    wsplit_kernel<<<128, 256>>>(W_in, W1);
    hmma_gemm_kernel<128, true, false><<<g128_grid, TB, SMEMG128>>>(
        x, wbh, wbl, b_in, h, nullptr, nullptr, M);

    // layer 1: GEMM + fused maxk -> compact t1 (needs souti)
    cudaStreamWaitEvent((cudaStream_t)0, e_scan, 0);
    hmma_gemm_kernel<128, false, true><<<g128_grid, TB, SMEMG128>>>(
        h, wbh + 16384, wbl + 16384, b1, nullptr, (float*)pt1v, (unsigned char*)pt1c, M);

    // z1 = t1 @ W2 (exact f32)
    spmm_kernel<128><<<spmm_grid, 512, SMEMS128>>>(
        (const float*)pt1v, (const unsigned char*)pt1c, W2, (float*)pz, M);

    // gather(z1) + folded bias + fused maxk -> compact t2 (needs eidx + cfold)
    cudaStreamWaitEvent((cudaStream_t)0, e_fill, 0);
    gather_maxk_kernel<<<warp_grid, TB>>>(M);

    // z2 = t2 @ Wo (exact f32)
    spmm_kernel<64><<<spmm_grid, 512, SMEMS64>>>(
        (const float*)pt2v, (const unsigned char*)pt2c, Wo, (float*)pz2, M);

    // out = gather(z2)*sini + c2
    gather_out_kernel<<<warp_grid, TB>>>(out, M);
}

// round 17
// speedup vs baseline: 1.0427x; 1.0427x over previous
#include <cuda_runtime.h>
#include <cuda_fp16.h>
#include <cstdint>

// ---------------- problem constants ----------------
#define NODES 100000
#define EDGES 1600000
#define HIDF  128
#define OUTF  64
#define KTOP  32

// ---------------- scratch (device globals; no allocation allowed) ----------
__device__ float g_h[(size_t)NODES * HIDF];        // dense activations (h0)
__device__ float g_z[(size_t)NODES * HIDF];        // z1 = t1 @ W2
__device__ float g_z2[(size_t)NODES * OUTF];       // z2 = t2 @ Wo
__device__ float g_t1v[(size_t)NODES * KTOP];      // compact t1 values (·souti)
__device__ unsigned char g_t1c[(size_t)NODES * KTOP];
__device__ float g_t2v[(size_t)NODES * KTOP];      // compact t2 values (·souti)
__device__ unsigned char g_t2c[(size_t)NODES * KTOP];
__device__ int   g_degout[NODES];
__device__ int   g_degin[NODES];
__device__ float g_souti[NODES];
__device__ float g_sini[NODES];
__device__ int   g_rowptr[NODES];
__device__ int   g_cursor[NODES];
__device__ int   g_eidx[EDGES];
__device__ int   g_bsum[128];
__device__ float g_c1[HIDF];                       // bg1@W2 + b2
__device__ float g_c2[OUTF];                       // bg2@Wo + bo
__device__ __half g_wbh[2 * 128 * 128];            // W_in^T, W1^T hi
__device__ __half g_wbl[2 * 128 * 128];            // lo

__device__ __forceinline__ uint32_t smem_to_u32(const void* smem_ptr) {
    uint32_t addr;
    asm("{ .reg .u64 tmp; cvta.to.shared.u64 tmp, %1; cvt.u32.u64 %0, tmp; }"
        : "=r"(addr) : "l"(smem_ptr));
    return addr;
}

__device__ __forceinline__ void ldsm_x4(uint32_t r[4], uint32_t addr) {
    asm volatile("ldmatrix.sync.aligned.m8n8.x4.shared.b16 {%0,%1,%2,%3}, [%4];"
        : "=r"(r[0]), "=r"(r[1]), "=r"(r[2]), "=r"(r[3]) : "r"(addr));
}

__device__ __forceinline__ void mma_fp16(float c[4], const uint32_t a[4],
                                         uint32_t b0, uint32_t b1) {
    asm volatile(
        "mma.sync.aligned.m16n8k16.row.col.f32.f16.f16.f32 "
        "{%0,%1,%2,%3}, {%4,%5,%6,%7}, {%8,%9}, {%0,%1,%2,%3};"
        : "+f"(c[0]), "+f"(c[1]), "+f"(c[2]), "+f"(c[3])
        : "r"(a[0]), "r"(a[1]), "r"(a[2]), "r"(a[3]), "r"(b0), "r"(b1));
}

// packed fp16 hi/lo split of 2 floats (bit-identical to scalar path)
__device__ __forceinline__ void split2(float2 p, uint32_t& hi, uint32_t& lo) {
    __half2 h = __float22half2_rn(p);
    float2 hb = __half22float2(h);
    __half2 l = __float22half2_rn(make_float2(p.x - hb.x, p.y - hb.y));
    hi = *(uint32_t*)&h;
    lo = *(uint32_t*)&l;
}

// exact top-32-of-128 threshold via bitwise radix select, warp-collective.
__device__ __forceinline__ unsigned topk_threshold(const unsigned key[4]) {
    unsigned thr = 0u;
#pragma unroll
    for (int b = 31; b >= 0; b--) {
        unsigned cand = thr | (1u << b);
        int local = (key[0] >= cand) + (key[1] >= cand)
                  + (key[2] >= cand) + (key[3] >= cand);
        int cnt = __reduce_add_sync(0xffffffffu, (unsigned)local);
        if (cnt >= KTOP) thr = cand;
    }
    return thr;
}

// ---------------- degree + CSR build kernels ----------------
__global__ void hist_kernel(const int* __restrict__ src, const int* __restrict__ dst, int E) {
    int e = blockIdx.x * blockDim.x + threadIdx.x;
    if (e < E) {
        atomicAdd(&g_degout[src[e]], 1);
        atomicAdd(&g_degin[dst[e]], 1);
    }
}

__global__ void __launch_bounds__(1024) scan_block_kernel(int n) {
    __shared__ int sh[1024];
    int tid = threadIdx.x;
    int i = blockIdx.x * 1024 + tid;
    int v = (i < n) ? g_degin[i] : 0;
    sh[tid] = v;
    __syncthreads();
#pragma unroll
    for (int off = 1; off < 1024; off <<= 1) {
        int t = (tid >= off) ? sh[tid - off] : 0;
        __syncthreads();
        sh[tid] += t;
        __syncthreads();
    }
    if (i < n) g_rowptr[i] = sh[tid] - v;
    if (tid == 1023) g_bsum[blockIdx.x] = sh[1023];
}

__global__ void __launch_bounds__(256) scan_add_kernel(int n, int nb) {
    __shared__ int sh[128];
    int tid = threadIdx.x;
    if (tid < 128) sh[tid] = (tid < nb) ? g_bsum[tid] : 0;
    __syncthreads();
#pragma unroll
    for (int off = 1; off < 128; off <<= 1) {
        int u = 0;
        if (tid < 128 && tid >= off) u = sh[tid - off];
        __syncthreads();
        if (tid < 128) sh[tid] += u;
        __syncthreads();
    }
    int i = blockIdx.x * blockDim.x + tid;
    if (i < n) {
        int blk = i >> 10;
        int base = (blk == 0) ? 0 : sh[blk - 1];
        int r = g_rowptr[i] + base;
        g_rowptr[i] = r;
        g_cursor[i] = r;
        int dout = g_degout[i]; if (dout < 1) dout = 1;
        int din  = g_degin[i];  if (din  < 1) din  = 1;
        g_souti[i] = rsqrtf((float)dout);
        g_sini[i]  = rsqrtf((float)din);
    }
}

__global__ void fill_kernel(const int* __restrict__ src, const int* __restrict__ dst, int E) {
    int e = blockIdx.x * blockDim.x + threadIdx.x;
    if (e < E) {
        int d = dst[e];
        int pos = atomicAdd(&g_cursor[d], 1);
        g_eidx[pos] = src[e];
    }
}

// ---------------- weight prep ------------------------------------------------
__global__ void wsplit_kernel(const float* __restrict__ W_in, const float* __restrict__ W1) {
    int i = blockIdx.x * blockDim.x + threadIdx.x;
    if (i >= 32768) return;
    int layer = i >> 14, idx = i & 16383;
    const float* W = layer ? W1 : W_in;
    int n = idx >> 7, k = idx & 127;
    float v = W[k * 128 + n];
    __half h = __float2half(v);
    __half l = __float2half(v - __half2float(h));
    g_wbh[(layer << 14) + n * 128 + k] = h;
    g_wbl[(layer << 14) + n * 128 + k] = l;
}

__global__ void __launch_bounds__(768) cfold_kernel(
    const float* __restrict__ bg1, const float* __restrict__ W2,
    const float* __restrict__ b2,
    const float* __restrict__ bg2, const float* __restrict__ Wo,
    const float* __restrict__ bo) {
    int wid  = threadIdx.x >> 5;
    int lane = threadIdx.x & 31;
    int o    = wid * 8 + (lane >> 2);
    int l4   = lane & 3;
    if (o < 128) {
        float acc = 0.f;
        for (int k = l4; k < 128; k += 4) acc += bg1[k] * W2[k * 128 + o];
        acc += __shfl_xor_sync(0xffffffffu, acc, 1);
        acc += __shfl_xor_sync(0xffffffffu, acc, 2);
        if (l4 == 0) g_c1[o] = acc + b2[o];
    } else if (o < 192) {
        int n = o - 128;
        float acc = 0.f;
        for (int k = l4; k < 128; k += 4) acc += bg2[k] * Wo[k * 64 + n];
        acc += __shfl_xor_sync(0xffffffffu, acc, 1);
        acc += __shfl_xor_sync(0xffffffffu, acc, 2);
        if (l4 == 0) g_c2[n] = acc + bo[n];
    }
}

// ---------------- HMMA fp16x3 GEMM (+ optional fused MaxK -> compact) -------
// rowbase: first node row handled by this launch (row-wise pipelining).
template <int BN, bool RELU, bool MAXK>
__global__ void __launch_bounds__(256, 2) hmma_gemm_kernel(
    const float* __restrict__ A,
    const __half* __restrict__ wbh,
    const __half* __restrict__ wbl,
    const float* __restrict__ bias,
    float* __restrict__ C,
    float* __restrict__ TV, unsigned char* __restrict__ TC,
    int rowbase, int M)
{
    static_assert(!MAXK || BN == 128, "fused maxk needs full rows per block");
    constexpr int NW = BN / 32;
    constexpr int MW = 8 / NW;
    constexpr int BM = MW * 32;
    constexpr int LDB = 272;
    constexpr int OFF_AH = 0;
    constexpr int OFF_AL = OFF_AH + BM * LDB;
    constexpr int OFF_WH = OFF_AL + BM * LDB;
    constexpr int OFF_WL = OFF_WH + BN * LDB;
    constexpr int OFF_BI = OFF_WL + BN * LDB;

    extern __shared__ char smem[];
    const uint32_t sb = smem_to_u32(smem);
    const int tid  = threadIdx.x;
    const int wid  = tid >> 5;
    const int lane = tid & 31;
    const int row0 = rowbase + blockIdx.x * BM;
    const int warp_m = wid / NW;
    const int warp_n = wid % NW;

    for (int i = tid; i < BN * 64; i += 256) {
        int n = i >> 6, kp = i & 63;
        ((uint32_t*)(smem + OFF_WH + n * LDB))[kp] = ((const uint32_t*)wbh)[i];
        ((uint32_t*)(smem + OFF_WL + n * LDB))[kp] = ((const uint32_t*)wbl)[i];
    }
    if (tid < BN) ((float*)(smem + OFF_BI))[tid] = bias[tid];

    for (int i = tid; i < BM * 32; i += 256) {
        int r = i >> 5, c4 = i & 31;
        float4 v = make_float4(0.f, 0.f, 0.f, 0.f);
        if (row0 + r < M) v = ((const float4*)A)[(size_t)(row0 + r) * 32 + c4];
        uint32_t h0, l0, h1, l1;
        split2(make_float2(v.x, v.y), h0, l0);
        split2(make_float2(v.z, v.w), h1, l1);
        uint32_t* dh = (uint32_t*)(smem + OFF_AH + r * LDB);
        uint32_t* dl = (uint32_t*)(smem + OFF_AL + r * LDB);
        dh[c4 * 2]     = h0;
        dh[c4 * 2 + 1] = h1;
        dl[c4 * 2]     = l0;
        dl[c4 * 2 + 1] = l1;
    }
    __syncthreads();

    const int a_row  = warp_m * 32 + (lane & 15);
    const int a_koff = (lane >> 4) * 8;
    const int b_row  = warp_n * 32 + (lane & 7) + ((lane >> 4) << 3);
    const int b_koff = ((lane >> 3) & 1) * 8;

    float acc[2][4][4];
#pragma unroll
    for (int mt = 0; mt < 2; mt++)
#pragma unroll
        for (int nt = 0; nt < 4; nt++)
#pragma unroll
            for (int q = 0; q < 4; q++) acc[mt][nt][q] = 0.f;

#pragma unroll
    for (int kt = 0; kt < 8; kt++) {
        const int kb = kt * 32 + a_koff * 2;
        uint32_t ah[2][4], al[2][4], wh[2][4], wl[2][4];
#pragma unroll
        for (int mt = 0; mt < 2; mt++) {
            uint32_t addr = sb + OFF_AH + (uint32_t)(a_row + mt * 16) * LDB + kb;
            ldsm_x4(ah[mt], addr);
            ldsm_x4(al[mt], addr + (OFF_AL - OFF_AH));
        }
        const int kbB = kt * 32 + b_koff * 2;
#pragma unroll
        for (int p = 0; p < 2; p++) {
            uint32_t addr = sb + OFF_WH + (uint32_t)(b_row + p * 16) * LDB + kbB;
            ldsm_x4(wh[p], addr);
            ldsm_x4(wl[p], addr + (OFF_WL - OFF_WH));
        }
#pragma unroll
        for (int mt = 0; mt < 2; mt++) {
#pragma unroll
            for (int p = 0; p < 2; p++) {
                mma_fp16(acc[mt][2 * p],     ah[mt], wh[p][0], wh[p][1]);
                mma_fp16(acc[mt][2 * p],     ah[mt], wl[p][0], wl[p][1]);
                mma_fp16(acc[mt][2 * p],     al[mt], wh[p][0], wh[p][1]);
                mma_fp16(acc[mt][2 * p + 1], ah[mt], wh[p][2], wh[p][3]);
                mma_fp16(acc[mt][2 * p + 1], ah[mt], wl[p][2], wl[p][3]);
                mma_fp16(acc[mt][2 * p + 1], al[mt], wh[p][2], wh[p][3]);
            }
        }
    }

    const float* bi = (const float*)(smem + OFF_BI);

    if (MAXK) {
        __syncthreads();
        float* rbuf = (float*)smem;          // [BM][132]
#pragma unroll
        for (int mt = 0; mt < 2; mt++) {
#pragma unroll
            for (int nt = 0; nt < 4; nt++) {
                int r   = warp_m * 32 + mt * 16 + (lane >> 2);
                int col = warp_n * 32 + nt * 8 + (lane & 3) * 2;
                float bx = bi[col], by = bi[col + 1];
                rbuf[r * 132 + col]           = acc[mt][nt][0] + bx;
                rbuf[r * 132 + col + 1]       = acc[mt][nt][1] + by;
                rbuf[(r + 8) * 132 + col]     = acc[mt][nt][2] + bx;
                rbuf[(r + 8) * 132 + col + 1] = acc[mt][nt][3] + by;
            }
        }
        __syncthreads();

        const unsigned lmlt = (1u << lane) - 1u;
#pragma unroll 1
        for (int rr = 0; rr < 8; rr++) {
            int r    = wid * 8 + rr;
            int grow = row0 + r;
            if (grow >= M) break;

            float v[4];
            unsigned key[4];
#pragma unroll
            for (int j = 0; j < 4; j++) {
                v[j] = rbuf[r * 132 + lane + 32 * j];
                unsigned u = __float_as_uint(v[j]);
                key[j] = (u & 0x80000000u) ? ~u : (u | 0x80000000u);
            }
            unsigned thr = topk_threshold(key);
            int rem;
            {
                int lg = (key[0] > thr) + (key[1] > thr)
                       + (key[2] > thr) + (key[3] > thr);
                rem = KTOP - (int)__reduce_add_sync(0xffffffffu, (unsigned)lg);
            }
            const float s = g_souti[grow];
            float* ov = TV + (size_t)grow * KTOP;
            unsigned char* oc = TC + (size_t)grow * KTOP;
            int off = 0;
#pragma unroll
            for (int j = 0; j < 4; j++) {
                unsigned beq = __ballot_sync(0xffffffffu, key[j] == thr);
                int neq  = __popc(beq);
                int take = rem < neq ? rem : neq;
                if (take < 0) take = 0;
                rem -= take;
                bool sel = (key[j] > thr) ||
                           ((key[j] == thr) && (__popc(beq & lmlt) < take));
                unsigned bsel = __ballot_sync(0xffffffffu, sel);
                if (sel) {
                    int pos = off + __popc(bsel & lmlt);
                    ov[pos] = v[j] * s;
                    oc[pos] = (unsigned char)(lane + 32 * j);
                }
                off += __popc(bsel);
            }
        }
    } else {
#pragma unroll
        for (int mt = 0; mt < 2; mt++) {
#pragma unroll
            for (int nt = 0; nt < 4; nt++) {
                int row = row0 + warp_m * 32 + mt * 16 + (lane >> 2);
                int col = warp_n * 32 + nt * 8 + (lane & 3) * 2;
                float bx = bi[col], by = bi[col + 1];
                float2 o0, o1;
                o0.x = acc[mt][nt][0] + bx; o0.y = acc[mt][nt][1] + by;
                o1.x = acc[mt][nt][2] + bx; o1.y = acc[mt][nt][3] + by;
                if (RELU) {
                    o0.x = fmaxf(o0.x, 0.f); o0.y = fmaxf(o0.y, 0.f);
                    o1.x = fmaxf(o1.x, 0.f); o1.y = fmaxf(o1.y, 0.f);
                }
                if (row < M)     *(float2*)&C[(size_t)row * BN + col] = o0;
                if (row + 8 < M) *(float2*)&C[(size_t)(row + 8) * BN + col] = o1;
            }
        }
    }
}

// ---------------- SPMM: 512 threads, 128 rows/block, rowbase offset ----------
template <int NC>
__global__ void __launch_bounds__(512) spmm_kernel(
    const float* __restrict__ tv, const unsigned char* __restrict__ tc,
    const float* __restrict__ W, float* __restrict__ Z, int rowbase, int M)
{
    constexpr int RPB = 128;
    extern __shared__ float smf[];
    float* ws = smf;                                 // [128][NC]
    float* sval = ws + 128 * NC;                     // [RPB][32]
    unsigned char* scol = (unsigned char*)(sval + RPB * 32);

    const int tid  = threadIdx.x;
    const int lane = tid & 31;
    const int wl   = tid >> 5;
    const int row0 = rowbase + blockIdx.x * RPB;

    for (int i = tid; i < 128 * NC / 4; i += 512)
        ((float4*)ws)[i] = ((const float4*)W)[i];
    {
        int base = row0 * KTOP;
        int lim  = (M - row0) * KTOP;
        if (lim > RPB * KTOP) lim = RPB * KTOP;
        for (int i = tid * 4; i < RPB * KTOP; i += 2048) {
            float4 v = make_float4(0.f, 0.f, 0.f, 0.f);
            uint32_t c = 0;
            if (i < lim) {
                v = *(const float4*)(tv + base + i);
                c = *(const uint32_t*)(tc + base + i);
            }
            *(float4*)(sval + i) = v;
            *(uint32_t*)(scol + i) = c;
        }
    }
    __syncthreads();

#pragma unroll 1
    for (int rr = 0; rr < 8; rr++) {
        const int lr  = wl * 8 + rr;
        const int row = row0 + lr;
        if (row >= M) break;

        const float* vrow = sval + lr * KTOP;
        const unsigned char* crow = scol + lr * KTOP;

        if (NC == 128) {
            float4 acc = make_float4(0.f, 0.f, 0.f, 0.f);
#pragma unroll
            for (int j = 0; j < KTOP; j++) {
                float vj = vrow[j];
                int   cj = crow[j];
                float4 w = ((const float4*)(ws + cj * NC))[lane];
                acc.x += vj * w.x;
                acc.y += vj * w.y;
                acc.z += vj * w.z;
                acc.w += vj * w.w;
            }
            ((float4*)(Z + (size_t)row * NC))[lane] = acc;
        } else {
            float2 acc = make_float2(0.f, 0.f);
#pragma unroll
            for (int j = 0; j < KTOP; j++) {
                float vj = vrow[j];
                int   cj = crow[j];
                float2 w = ((const float2*)(ws + cj * NC))[lane];
                acc.x += vj * w.x;
                acc.y += vj * w.y;
            }
            ((float2*)(Z + (size_t)row * NC))[lane] = acc;
        }
    }
}

// ---------------- gather (128 cols) + fused MaxK -> compact t2 ---------------
__global__ void __launch_bounds__(256) gather_maxk_kernel(int rowbase, int M) {
    __shared__ float rbuf[8][128];
    int w    = rowbase + ((blockIdx.x * blockDim.x + threadIdx.x) >> 5);
    int lane = threadIdx.x & 31;
    int wl   = threadIdx.x >> 5;
    if (w >= M) return;

    float acc0 = 0.f, acc1 = 0.f, acc2 = 0.f, acc3 = 0.f;
    const int beg = g_rowptr[w];
    const int end = beg + g_degin[w];
    const float4* tp = (const float4*)g_z;

    int e = beg;
    for (; e + 8 <= end; e += 8) {
        int s[8];
#pragma unroll
        for (int q = 0; q < 8; q++) s[q] = __ldg(&g_eidx[e + q]);
        float4 v[8];
#pragma unroll
        for (int q = 0; q < 8; q++) v[q] = __ldg(&tp[(size_t)s[q] * 32 + lane]);
#pragma unroll
        for (int q = 0; q < 8; q++) {
            acc0 += v[q].x; acc1 += v[q].y; acc2 += v[q].z; acc3 += v[q].w;
        }
    }
    for (; e < end; e++) {
        int s0 = __ldg(&g_eidx[e]);
        float4 v0 = __ldg(&tp[(size_t)s0 * 32 + lane]);
        acc0 += v0.x; acc1 += v0.y; acc2 += v0.z; acc3 += v0.w;
    }

    const float sc = g_sini[w];
    float4 b = __ldg(&((const float4*)g_c1)[lane]);
    rbuf[wl][lane * 4]     = acc0 * sc + b.x;
    rbuf[wl][lane * 4 + 1] = acc1 * sc + b.y;
    rbuf[wl][lane * 4 + 2] = acc2 * sc + b.z;
    rbuf[wl][lane * 4 + 3] = acc3 * sc + b.w;
    __syncwarp();

    float v[4];
    unsigned key[4];
#pragma unroll
    for (int j = 0; j < 4; j++) {
        v[j] = rbuf[wl][lane + 32 * j];
        unsigned u = __float_as_uint(v[j]);
        key[j] = (u & 0x80000000u) ? ~u : (u | 0x80000000u);
    }
    unsigned thr = topk_threshold(key);
    int rem;
    {
        int lg = (key[0] > thr) + (key[1] > thr)
               + (key[2] > thr) + (key[3] > thr);
        rem = KTOP - (int)__reduce_add_sync(0xffffffffu, (unsigned)lg);
    }
    const float s = g_souti[w];
    const unsigned lmlt = (1u << lane) - 1u;
    float* ov = g_t2v + (size_t)w * KTOP;
    unsigned char* oc = g_t2c + (size_t)w * KTOP;
    int off = 0;
#pragma unroll
    for (int j = 0; j < 4; j++) {
        unsigned beq = __ballot_sync(0xffffffffu, key[j] == thr);
        int neq  = __popc(beq);
        int take = rem < neq ? rem : neq;
        if (take < 0) take = 0;
        rem -= take;
        bool sel = (key[j] > thr) ||
                   ((key[j] == thr) && (__popc(beq & lmlt) < take));
        unsigned bsel = __ballot_sync(0xffffffffu, sel);
        if (sel) {
            int pos = off + __popc(bsel & lmlt);
            ov[pos] = v[j] * s;
            oc[pos] = (unsigned char)(lane + 32 * j);
        }
        off += __popc(bsel);
    }
}

// ---------------- final gather (64 cols) -> d_out ----------------------------
__global__ void __launch_bounds__(256) gather_out_kernel(float* __restrict__ out, int M) {
    int w    = (blockIdx.x * blockDim.x + threadIdx.x) >> 5;
    int lane = threadIdx.x & 31;
    if (w >= M) return;

    float acc0 = 0.f, acc1 = 0.f;
    const int beg = g_rowptr[w];
    const int end = beg + g_degin[w];
    const float2* tp = (const float2*)g_z2;

    int e = beg;
    for (; e + 8 <= end; e += 8) {
        int s[8];
#pragma unroll
        for (int q = 0; q < 8; q++) s[q] = __ldg(&g_eidx[e + q]);
        float2 v[8];
#pragma unroll
        for (int q = 0; q < 8; q++) v[q] = __ldg(&tp[(size_t)s[q] * 32 + lane]);
#pragma unroll
        for (int q = 0; q < 8; q++) { acc0 += v[q].x; acc1 += v[q].y; }
    }
    for (; e < end; e++) {
        int s0 = __ldg(&g_eidx[e]);
        float2 v0 = __ldg(&tp[(size_t)s0 * 32 + lane]);
        acc0 += v0.x; acc1 += v0.y;
    }

    const float sc = g_sini[w];
    float2 b = __ldg(&((const float2*)g_c2)[lane]);
    float2 o;
    o.x = acc0 * sc + b.x;
    o.y = acc1 * sc + b.y;
    ((float2*)(out + (size_t)w * OUTF))[lane] = o;
}

// ---------------- launch -----------------------------------------------------
extern "C" void kernel_launch(void* const* d_in, const int* in_sizes, int n_in,
                              void* d_out, int out_size) {
    const float* x    = (const float*)d_in[0];
    const int*   src  = (const int*)d_in[1];
    const int*   dst  = (const int*)d_in[2];
    const float* W_in = (const float*)d_in[3];
    const float* b_in = (const float*)d_in[4];
    const float* W1   = (const float*)d_in[5];
    const float* b1   = (const float*)d_in[6];
    const float* bg1  = (const float*)d_in[7];
    const float* W2   = (const float*)d_in[8];
    const float* b2   = (const float*)d_in[9];
    const float* bg2  = (const float*)d_in[10];
    const float* Wo   = (const float*)d_in[11];
    const float* bo   = (const float*)d_in[12];
    float* out = (float*)d_out;

    const int M = in_sizes[0] / HIDF;   // 100000
    const int E = in_sizes[1];          // 1600000

    static bool s_init = false;
    static cudaStream_t s1, s2;
    static cudaEvent_t e_root, e_scan, e_fill, e_w, e_z1a, e_z1b, e_z2b;
    if (!s_init) {
        cudaStreamCreateWithFlags(&s1, cudaStreamNonBlocking);
        cudaStreamCreateWithFlags(&s2, cudaStreamNonBlocking);
        cudaEventCreateWithFlags(&e_root, cudaEventDisableTiming);
        cudaEventCreateWithFlags(&e_scan, cudaEventDisableTiming);
        cudaEventCreateWithFlags(&e_fill, cudaEventDisableTiming);
        cudaEventCreateWithFlags(&e_w,    cudaEventDisableTiming);
        cudaEventCreateWithFlags(&e_z1a,  cudaEventDisableTiming);
        cudaEventCreateWithFlags(&e_z1b,  cudaEventDisableTiming);
        cudaEventCreateWithFlags(&e_z2b,  cudaEventDisableTiming);
        s_init = true;
    }

    const int SMEMG128 = (64 + 128) * 2 * 272 + 128 * 4;           // 104960
    const int SMEMS128 = 128 * 128 * 4 + 128 * 32 * 4 + 128 * 32;  // 86016
    const int SMEMS64  = 128 * 64 * 4  + 128 * 32 * 4 + 128 * 32;  // 53248
    cudaFuncSetAttribute((const void*)hmma_gemm_kernel<128, true,  false>, cudaFuncAttributeMaxDynamicSharedMemorySize, SMEMG128);
    cudaFuncSetAttribute((const void*)hmma_gemm_kernel<128, false, true>,  cudaFuncAttributeMaxDynamicSharedMemorySize, SMEMG128);
    cudaFuncSetAttribute((const void*)spmm_kernel<128>, cudaFuncAttributeMaxDynamicSharedMemorySize, SMEMS128);
    cudaFuncSetAttribute((const void*)spmm_kernel<64>,  cudaFuncAttributeMaxDynamicSharedMemorySize, SMEMS64);

    void *ph, *pz, *pz2, *pt1v, *pt1c, *pt2v, *pt2c, *pdo, *pdi, *pwbh, *pwbl;
    cudaGetSymbolAddress(&ph,   g_h);
    cudaGetSymbolAddress(&pz,   g_z);
    cudaGetSymbolAddress(&pz2,  g_z2);
    cudaGetSymbolAddress(&pt1v, g_t1v);
    cudaGetSymbolAddress(&pt1c, g_t1c);
    cudaGetSymbolAddress(&pt2v, g_t2v);
    cudaGetSymbolAddress(&pt2c, g_t2c);
    cudaGetSymbolAddress(&pdo,  g_degout);
    cudaGetSymbolAddress(&pdi,  g_degin);
    cudaGetSymbolAddress(&pwbh, g_wbh);
    cudaGetSymbolAddress(&pwbl, g_wbl);
    float* h = (float*)ph;
    __half* wbh = (__half*)pwbh;
    __half* wbl = (__half*)pwbl;

    const int TB = 256;
    const int node_grid = (M + TB - 1) / TB;
    const int edge_grid = (E + TB - 1) / TB;
    const int NB        = (M + 1023) / 1024;

    // row halves (128-aligned so gemm/spmm blocks never straddle)
    const int M0 = 50048;               // 391 * 128
    const int M1 = M - M0;              // 49952
    const int gg0 = M0 / 64;                       // 782
    const int gg1 = (M1 + 63) / 64;                // 781
    const int sg0 = M0 / 128;                      // 391
    const int sg1 = (M1 + 127) / 128;              // 391
    const int wg0 = (M0 * 32 + TB - 1) / TB;
    const int wg1 = (M1 * 32 + TB - 1) / TB;
    const int warp_grid = (M * 32 + TB - 1) / TB;

    // ---- side stream: CSR build (+ cfold at tail) ----
    cudaEventRecord(e_root, 0);
    cudaStreamWaitEvent(s1, e_root, 0);
    cudaStreamWaitEvent(s2, e_root, 0);
    cudaMemsetAsync(pdo, 0, (size_t)M * sizeof(int), s1);
    cudaMemsetAsync(pdi, 0, (size_t)M * sizeof(int), s1);
    hist_kernel<<<edge_grid, TB, 0, s1>>>(src, dst, E);
    scan_block_kernel<<<NB, 1024, 0, s1>>>(M);
    scan_add_kernel<<<node_grid, TB, 0, s1>>>(M, NB);
    cudaEventRecord(e_scan, s1);
    fill_kernel<<<edge_grid, TB, 0, s1>>>(src, dst, E);
    cfold_kernel<<<1, 768, 0, s1>>>(bg1, W2, b2, bg2, Wo, bo);
    cudaEventRecord(e_fill, s1);

    // ---- main stream 0: weight split, then half-0 wavefront ----
    wsplit_kernel<<<128, 256>>>(W_in, W1);
    cudaEventRecord(e_w, 0);
    cudaStreamWaitEvent(s2, e_w, 0);

    // stage A: input projection
    hmma_gemm_kernel<128, true, false><<<gg0, TB, SMEMG128>>>(
        x, wbh, wbl, b_in, h, nullptr, nullptr, 0, M0);
    hmma_gemm_kernel<128, true, false><<<gg1, TB, SMEMG128, s2>>>(
        x, wbh, wbl, b_in, h, nullptr, nullptr, M0, M);

    // stage B: layer-1 GEMM + fused maxk (needs souti)
    cudaStreamWaitEvent((cudaStream_t)0, e_scan, 0);
    cudaStreamWaitEvent(s2, e_scan, 0);
    hmma_gemm_kernel<128, false, true><<<gg0, TB, SMEMG128>>>(
        h, wbh + 16384, wbl + 16384, b1, nullptr, (float*)pt1v, (unsigned char*)pt1c, 0, M0);
    hmma_gemm_kernel<128, false, true><<<gg1, TB, SMEMG128, s2>>>(
        h, wbh + 16384, wbl + 16384, b1, nullptr, (float*)pt1v, (unsigned char*)pt1c, M0, M);

    // stage C: z1 = t1 @ W2
    spmm_kernel<128><<<sg0, 512, SMEMS128>>>(
        (const float*)pt1v, (const unsigned char*)pt1c, W2, (float*)pz, 0, M0);
    cudaEventRecord(e_z1a, 0);
    spmm_kernel<128><<<sg1, 512, SMEMS128, s2>>>(
        (const float*)pt1v, (const unsigned char*)pt1c, W2, (float*)pz, M0, M);
    cudaEventRecord(e_z1b, s2);

    // stage D: gather + fused maxk (needs ALL z1 + eidx + c1)
    cudaStreamWaitEvent((cudaStream_t)0, e_fill, 0);
    cudaStreamWaitEvent((cudaStream_t)0, e_z1b, 0);
    cudaStreamWaitEvent(s2, e_fill, 0);
    cudaStreamWaitEvent(s2, e_z1a, 0);
    gather_maxk_kernel<<<wg0, TB>>>(0, M0);
    gather_maxk_kernel<<<wg1, TB, 0, s2>>>(M0, M);

    // stage E: z2 = t2 @ Wo
    spmm_kernel<64><<<sg0, 512, SMEMS64>>>(
        (const float*)pt2v, (const unsigned char*)pt2c, Wo, (float*)pz2, 0, M0);
    spmm_kernel<64><<<sg1, 512, SMEMS64, s2>>>(
        (const float*)pt2v, (const unsigned char*)pt2c, Wo, (float*)pz2, M0, M);
    cudaEventRecord(e_z2b, s2);

    // stage F: out = gather(z2)*sini + c2 (needs ALL z2)
    cudaStreamWaitEvent((cudaStream_t)0, e_z2b, 0);
    gather_out_kernel<<<warp_grid, TB>>>(out, M);
}